// round 17
// baseline (speedup 1.0000x reference)
#include <cuda_runtime.h>
#include <cuda_fp16.h>
#include <cstdint>

// Shapes (fixed): B=4, S=2048, D=1024, H=16, dk=64.
#define MDIM 8192
#define NDIM 1024
#define KDIM 1024
#define NCTA 296                          // 2 CTAs/SM x 148 SMs, all resident
#define NWEL ((size_t)NDIM * KDIM)        // elements per weight matrix (1M)

// ---------------------------------------------------------------------------
// Device scratch (allocation-free per harness rules)
// ---------------------------------------------------------------------------
__device__ __half g_X[3][MDIM * NDIM];    // fp16 activations (slot 0 reused for ctx)
__device__ __half g_WT[4][NDIM * KDIM];   // transposed weights, fp16
__device__ __half g_Qh[MDIM * NDIM];
__device__ __half g_Kh[MDIM * NDIM];
__device__ __half g_Vh[MDIM * NDIM];
__device__ unsigned g_bar = 0;            // monotonic barrier counter (never reset)

#define QSCALE 0.18033688011112042f       // 0.125 * log2(e), folded into Q

// ---------------------------------------------------------------------------
// Helpers
// ---------------------------------------------------------------------------
__device__ __forceinline__ uint32_t smem_u32(const void* p) {
    uint32_t a;
    asm("{ .reg .u64 t; cvta.to.shared.u64 t, %1; cvt.u32.u64 %0, t; }"
        : "=r"(a) : "l"(p));
    return a;
}

__device__ __forceinline__ float ex2f(float x) {
    float y;
    asm("ex2.approx.f32 %0, %1;" : "=f"(y) : "f"(x));
    return y;
}

__device__ __forceinline__ void mma_f16(float* c, const uint32_t* a,
                                        uint32_t b0, uint32_t b1) {
    asm volatile(
        "mma.sync.aligned.m16n8k16.row.col.f32.f16.f16.f32 "
        "{%0,%1,%2,%3}, {%4,%5,%6,%7}, {%8,%9}, {%0,%1,%2,%3};"
        : "+f"(c[0]), "+f"(c[1]), "+f"(c[2]), "+f"(c[3])
        : "r"(a[0]), "r"(a[1]), "r"(a[2]), "r"(a[3]), "r"(b0), "r"(b1));
}

__device__ __forceinline__ void ldsm_x4(uint32_t& d0, uint32_t& d1,
                                        uint32_t& d2, uint32_t& d3, uint32_t a) {
    asm volatile("ldmatrix.sync.aligned.m8n8.x4.shared.b16 {%0,%1,%2,%3}, [%4];"
                 : "=r"(d0), "=r"(d1), "=r"(d2), "=r"(d3) : "r"(a));
}
__device__ __forceinline__ void ldsm_x4_t(uint32_t& d0, uint32_t& d1,
                                          uint32_t& d2, uint32_t& d3, uint32_t a) {
    asm volatile("ldmatrix.sync.aligned.m8n8.x4.trans.shared.b16 {%0,%1,%2,%3}, [%4];"
                 : "=r"(d0), "=r"(d1), "=r"(d2), "=r"(d3) : "r"(a));
}

__device__ __forceinline__ void cp_async16(uint32_t dst, const void* src) {
    asm volatile("cp.async.cg.shared.global [%0], [%1], 16;"
                 :: "r"(dst), "l"(src) : "memory");
}
__device__ __forceinline__ void cp_commit() {
    asm volatile("cp.async.commit_group;" ::: "memory");
}
template <int N>
__device__ __forceinline__ void cp_wait() {
    asm volatile("cp.async.wait_group %0;" :: "n"(N) : "memory");
}

// Grid-wide barrier: generation-based, monotonic counter, graph-replay safe.
__device__ __forceinline__ void grid_barrier(int tid) {
    __syncthreads();
    if (tid == 0) {
        __threadfence();                              // release all prior writes
        unsigned old = atomicAdd(&g_bar, 1u);
        unsigned target = (old / NCTA + 1u) * NCTA;
        unsigned cur;
        do {
            asm volatile("ld.acquire.gpu.u32 %0, [%1];"
                         : "=r"(cur) : "l"(&g_bar));
        } while (cur < target);
    }
    __syncthreads();
}

// ---------------------------------------------------------------------------
// Phase 0 tile: z<4 -> 32x32 weight transpose block; z>=4 -> activation cvt.
// ---------------------------------------------------------------------------
__device__ void prep_tile(int t, const float* const* w, __half* wt,
                          const float* const* x, __half* const* xd,
                          char* smem, int tid)
{
    const int z = t >> 10;            // 0..6
    const int rem = t & 1023;
    const int bx = rem & 31;
    const int by = rem >> 5;
    const int tx = tid & 31;
    const int ty = tid >> 5;          // 0..7

    if (z < 4) {
        float (*tt)[33] = (float(*)[33])smem;
        const float* W = w[z];
        __half* D = wt + (size_t)z * NWEL;
        int xcol = bx * 32 + tx;
        int y0 = by * 32;
#pragma unroll
        for (int j = 0; j < 32; j += 8)
            tt[ty + j][tx] = W[(size_t)(y0 + ty + j) * 1024 + xcol];
        __syncthreads();
        int x2 = by * 32 + tx;
        int y2 = bx * 32;
#pragma unroll
        for (int j = 0; j < 32; j += 8)
            D[(size_t)(y2 + ty + j) * 1024 + x2] = __float2half_rn(tt[tx][ty + j]);
        __syncthreads();              // protect smem before next tile reuses it
    } else {
        const float* X = x[z - 4];
        __half* H = xd[z - 4];
        size_t base = ((size_t)rem * 256 + tid) * 4;
        const size_t stride = (size_t)1024 * 256 * 4;
#pragma unroll
        for (int it = 0; it < 8; it++) {
            size_t i = base + (size_t)it * stride;
            float4 v = *(const float4*)(X + i);
            __half2 h01 = __floats2half2_rn(v.x, v.y);
            __half2 h23 = __floats2half2_rn(v.z, v.w);
            uint2 pk;
            pk.x = *(uint32_t*)&h01;
            pk.y = *(uint32_t*)&h23;
            *(uint2*)(H + i) = pk;
        }
    }
}

// ---------------------------------------------------------------------------
// GEMM tile (verified R15 body): C = A @ B^T, CTA 128x128, BK=64, 3-stage.
// mode 0: C f32;  mode 2: D1 fp16 scaled.
// ---------------------------------------------------------------------------
#define WROW 36
#define TILEW (128 * WROW)
#define STW (2 * TILEW)
#define NBUF 3
#define SMEM_MAX (NBUF * STW * 4)          // 110592 bytes

__device__ __forceinline__ void gemm_load_stage(
    const __half* __restrict__ A, const __half* __restrict__ B,
    int s, uint32_t sbase, int tid)
{
#pragma unroll
    for (int i = 0; i < 4; i++) {
        const int idx = tid + i * 256;
        const int r = idx >> 3;
        const int c = idx & 7;
        const uint32_t doff = (uint32_t)(r * WROW + c * 4) * 4;
        const size_t goff = (size_t)r * KDIM + s * 64 + c * 8;
        cp_async16(sbase + doff,             A + goff);
        cp_async16(sbase + TILEW * 4 + doff, B + goff);
    }
    cp_commit();
}

__device__ void gemm_tile(const __half* __restrict__ Abase,
                          const __half* __restrict__ Bbase,
                          float* __restrict__ C, __half* __restrict__ D1,
                          float scl, int mode, int bx, int by,
                          char* smem, int tid)
{
    uint32_t* sw = (uint32_t*)smem;
    const int lane = tid & 31;
    const int wid = tid >> 5;
    const int wm = wid >> 2;
    const int wn = wid & 3;
    const int r0 = lane >> 2;
    const int c0 = lane & 3;

    const __half* A = Abase + (size_t)by * 128 * KDIM;
    const __half* Bw = Bbase + (size_t)bx * 128 * KDIM;
    const uint32_t sbase = smem_u32(sw);

    float acc[4][4][4];
#pragma unroll
    for (int i = 0; i < 4; i++)
#pragma unroll
        for (int j = 0; j < 4; j++)
#pragma unroll
            for (int k = 0; k < 4; k++) acc[i][j][k] = 0.0f;

    gemm_load_stage(A, Bw, 0, sbase + 0 * STW * 4, tid);
    gemm_load_stage(A, Bw, 1, sbase + 1 * STW * 4, tid);

    const int NST = KDIM / 64;
    for (int s = 0; s < NST; s++) {
        if (s + 1 < NST) cp_wait<1>();
        else             cp_wait<0>();
        __syncthreads();
        if (s + 2 < NST)
            gemm_load_stage(A, Bw, s + 2, sbase + ((s + 2) % NBUF) * STW * 4, tid);
        const uint32_t* St = sw + (s % NBUF) * STW;

#pragma unroll
        for (int ks = 0; ks < 4; ks++) {
            uint32_t af[4][4], bf[4][2];
#pragma unroll
            for (int nt = 0; nt < 4; nt++) {
                const int n = wn * 32 + nt * 8 + r0;
                const int nb = TILEW + n * WROW + ks * 8 + c0;
                bf[nt][0] = St[nb];
                bf[nt][1] = St[nb + 4];
            }
#pragma unroll
            for (int mt = 0; mt < 4; mt++) {
                const int row = wm * 64 + mt * 16 + r0;
                const int base = row * WROW + ks * 8 + c0;
                af[mt][0] = St[base];
                af[mt][1] = St[base + 8 * WROW];
                af[mt][2] = St[base + 4];
                af[mt][3] = St[base + 8 * WROW + 4];
            }
#pragma unroll
            for (int mt = 0; mt < 4; mt++)
#pragma unroll
                for (int nt = 0; nt < 4; nt++)
                    mma_f16(acc[mt][nt], af[mt], bf[nt][0], bf[nt][1]);
        }
    }
    __syncthreads();                  // retire smem before next tile reuses it

    const size_t crow0 = (size_t)by * 128 + wm * 64;
    const size_t ccol0 = (size_t)bx * 128 + wn * 32;
#pragma unroll
    for (int mt = 0; mt < 4; mt++) {
#pragma unroll
        for (int nt = 0; nt < 4; nt++) {
            const size_t row = crow0 + mt * 16 + r0;
            const size_t col = ccol0 + nt * 8 + c0 * 2;
            float* c = acc[mt][nt];
            if (mode == 0) {
                *(float2*)(C + row * NDIM + col)       = make_float2(c[0], c[1]);
                *(float2*)(C + (row + 8) * NDIM + col) = make_float2(c[2], c[3]);
            } else {
                __half2 h01 = __floats2half2_rn(c[0] * scl, c[1] * scl);
                __half2 h23 = __floats2half2_rn(c[2] * scl, c[3] * scl);
                *(__half2*)(D1 + row * NDIM + col)       = h01;
                *(__half2*)(D1 + (row + 8) * NDIM + col) = h23;
            }
        }
    }
}

// ---------------------------------------------------------------------------
// Attention tile (verified R15 body): 128 queries of one (b,h); 16 rows/warp;
// 128-key stages as two 64-key halves; pipelined ldsm; P = ex2(S) in regs.
// ---------------------------------------------------------------------------
#define HKS 72
#define KVSTG (2 * 128 * HKS)
#define NKBUF 3
// NKBUF * KVSTG * 2 = 110592 == SMEM_MAX

__device__ __forceinline__ void attn_load_kv16(
    const __half* __restrict__ Kg, const __half* __restrict__ Vg,
    int t, uint32_t stg_base, int tid)
{
    const uint32_t kb = stg_base;
    const uint32_t vb = stg_base + 128 * HKS * 2;
#pragma unroll
    for (int i = 0; i < 4; i++) {
        int idx = tid + i * 256;
        int r = idx >> 3;
        int c = idx & 7;
        const uint32_t doff = (uint32_t)(r * HKS + c * 8) * 2;
        cp_async16(kb + doff, Kg + (size_t)(t * 128 + r) * 64 + c * 8);
        cp_async16(vb + doff, Vg + (size_t)(t * 128 + r) * 64 + c * 8);
    }
    cp_commit();
}

__device__ void attn_tile(const __half* __restrict__ Qh,
                          const __half* __restrict__ Kh,
                          const __half* __restrict__ Vh,
                          __half* __restrict__ Oh,
                          int bx, int h, int b, char* smem, int tid)
{
    __half* hsm = (__half*)smem;
    const int lane = tid & 31;
    const int w = tid >> 5;
    const int r0 = lane >> 2;
    const int c0 = lane & 3;
    const int qbase = bx * 128;
    const size_t off = ((size_t)b * 2048 + h * 128) * 1024;

    const __half* Qg = Qh + off;
    const __half* Kg = Kh + off;
    const __half* Vg = Vh + off;
    const uint32_t sb = smem_u32(hsm);

    const uint32_t koff = (uint32_t)((lane & 7) * HKS + (lane >> 3) * 8) * 2;
    const uint32_t voff = (uint32_t)((((lane >> 3) & 1) * 8 + (lane & 7)) * HKS +
                                     (lane >> 4) * 8) * 2;

    uint32_t qf[4][4];
    const int row0 = qbase + w * 16 + r0;
#pragma unroll
    for (int kg = 0; kg < 4; kg++)
#pragma unroll
        for (int q = 0; q < 4; q++) {
            int row = row0 + (q & 1) * 8;
            int col = kg * 16 + (q >> 1) * 8 + 2 * c0;
            qf[kg][q] = *(const uint32_t*)(Qg + (size_t)row * 64 + col);
        }

    float oacc[8][4];
#pragma unroll
    for (int nt = 0; nt < 8; nt++)
#pragma unroll
        for (int j = 0; j < 4; j++) oacc[nt][j] = 0.0f;
    float ls0 = 0.f, ls1 = 0.f;

    attn_load_kv16(Kg, Vg, 0, sb + 0 * KVSTG * 2, tid);
    attn_load_kv16(Kg, Vg, 1, sb + 1 * KVSTG * 2, tid);

    for (int t = 0; t < 16; t++) {
        if (t + 1 < 16) cp_wait<1>();
        else            cp_wait<0>();
        __syncthreads();
        if (t + 2 < 16)
            attn_load_kv16(Kg, Vg, t + 2, sb + ((t + 2) % NKBUF) * KVSTG * 2, tid);

        const uint32_t stg = sb + (uint32_t)((t % NKBUF) * KVSTG) * 2;

#pragma unroll
        for (int half = 0; half < 2; half++) {
            const uint32_t kbase = stg + (uint32_t)(half * 64 * HKS) * 2 + koff;
            const uint32_t vbase = stg + (uint32_t)(128 * HKS + half * 64 * HKS) * 2 + voff;

            float sacc[8][4];
#pragma unroll
            for (int nt = 0; nt < 8; nt++)
#pragma unroll
                for (int j = 0; j < 4; j++) sacc[nt][j] = 0.0f;

            uint32_t bk[2][4][2];
            ldsm_x4(bk[0][0][0], bk[0][0][1], bk[0][1][0], bk[0][1][1], kbase + 0);
            ldsm_x4(bk[0][2][0], bk[0][2][1], bk[0][3][0], bk[0][3][1], kbase + 32 * 2);
#pragma unroll
            for (int nt = 0; nt < 8; nt++) {
                const int cur = nt & 1;
                if (nt < 7) {
                    const int nxt = cur ^ 1;
                    const uint32_t a = kbase + (uint32_t)((nt + 1) * 8 * HKS) * 2;
                    ldsm_x4(bk[nxt][0][0], bk[nxt][0][1], bk[nxt][1][0], bk[nxt][1][1],
                            a + 0);
                    ldsm_x4(bk[nxt][2][0], bk[nxt][2][1], bk[nxt][3][0], bk[nxt][3][1],
                            a + 32 * 2);
                }
#pragma unroll
                for (int kg = 0; kg < 4; kg++)
                    mma_f16(sacc[nt], qf[kg], bk[cur][kg][0], bk[cur][kg][1]);
            }

            uint32_t pfrag[4][4];
#pragma unroll
            for (int nt = 0; nt < 8; nt++) {
                float p0 = ex2f(sacc[nt][0]);
                float p1 = ex2f(sacc[nt][1]);
                float p2 = ex2f(sacc[nt][2]);
                float p3 = ex2f(sacc[nt][3]);
                ls0 += p0 + p1;
                ls1 += p2 + p3;
                __half2 h01 = __floats2half2_rn(p0, p1);
                __half2 h23 = __floats2half2_rn(p2, p3);
                pfrag[nt >> 1][(nt & 1) * 2 + 0] = *(uint32_t*)&h01;
                pfrag[nt >> 1][(nt & 1) * 2 + 1] = *(uint32_t*)&h23;
            }

            uint32_t bv[2][4];
            ldsm_x4_t(bv[0][0], bv[0][1], bv[0][2], bv[0][3], vbase);
#pragma unroll
            for (int idx = 0; idx < 16; idx++) {
                const int cur = idx & 1;
                if (idx < 15) {
                    const int ni = idx + 1;
                    const uint32_t a = vbase +
                        (uint32_t)(((ni >> 2) * 16) * HKS + (ni & 3) * 16) * 2;
                    ldsm_x4_t(bv[cur ^ 1][0], bv[cur ^ 1][1],
                              bv[cur ^ 1][2], bv[cur ^ 1][3], a);
                }
                const int kg = idx >> 2;
                const int p = idx & 3;
                mma_f16(oacc[2 * p],     pfrag[kg], bv[cur][0], bv[cur][1]);
                mma_f16(oacc[2 * p + 1], pfrag[kg], bv[cur][2], bv[cur][3]);
            }
        }
    }
    __syncthreads();                  // retire smem before next tile reuses it

    ls0 += __shfl_xor_sync(0xffffffffu, ls0, 1);
    ls0 += __shfl_xor_sync(0xffffffffu, ls0, 2);
    ls1 += __shfl_xor_sync(0xffffffffu, ls1, 1);
    ls1 += __shfl_xor_sync(0xffffffffu, ls1, 2);
    const float inv0 = 1.0f / ls0;
    const float inv1 = 1.0f / ls1;

#pragma unroll
    for (int nt = 0; nt < 8; nt++) {
        const int col = h * 64 + nt * 8 + 2 * c0;
        __half2 hh01 = __floats2half2_rn(oacc[nt][0] * inv0, oacc[nt][1] * inv0);
        __half2 hh23 = __floats2half2_rn(oacc[nt][2] * inv1, oacc[nt][3] * inv1);
        *(__half2*)(Oh + ((size_t)(b * 2048 + row0)) * 1024 + col)     = hh01;
        *(__half2*)(Oh + ((size_t)(b * 2048 + row0 + 8)) * 1024 + col) = hh23;
    }
}

// ---------------------------------------------------------------------------
// Fused persistent kernel: prep -> QKV gemm -> attention -> out-proj,
// separated by grid barriers. 296 CTAs, all resident (2/SM).
// ---------------------------------------------------------------------------
struct FusedArgs {
    const float* w[4];
    const float* x[3];
    __half *WT, *X, *Qh, *Kh, *Vh;
    float* out;
};

__global__ void __launch_bounds__(256, 2) fused_kernel(FusedArgs fa)
{
    extern __shared__ char smem[];
    const int tid = threadIdx.x;
    const int cta = blockIdx.x;
    const size_t NEL = (size_t)MDIM * NDIM;

    __half* xd[3] = { fa.X, fa.X + NEL, fa.X + 2 * NEL };

    // Phase 0: prep (7168 tiles)
    for (int t = cta; t < 7168; t += NCTA)
        prep_tile(t, fa.w, fa.WT, fa.x, xd, smem, tid);
    grid_barrier(tid);

    // Phase 1: Q/K/V projections (1536 tiles: z*512 + by*8 + bx)
    for (int t = cta; t < 1536; t += NCTA) {
        const int z = t >> 9;
        const int rem = t & 511;
        const int by = rem >> 3;
        const int bx = rem & 7;
        __half* D1 = (z == 0) ? fa.Qh : (z == 1) ? fa.Kh : fa.Vh;
        const float scl = (z == 0) ? QSCALE : 1.0f;
        gemm_tile(fa.X + (size_t)z * NEL, fa.WT + (size_t)z * NWEL,
                  nullptr, D1, scl, 2, bx, by, smem, tid);
    }
    grid_barrier(tid);

    // Phase 2: attention (1024 tiles: b*256 + h*16 + bx) -> ctx into X slot 0
    for (int t = cta; t < 1024; t += NCTA) {
        const int bx = t & 15;
        const int h = (t >> 4) & 15;
        const int b = t >> 8;
        attn_tile(fa.Qh, fa.Kh, fa.Vh, fa.X, bx, h, b, smem, tid);
    }
    grid_barrier(tid);

    // Phase 3: output projection (512 tiles: by*8 + bx)
    for (int t = cta; t < 512; t += NCTA) {
        const int by = t >> 3;
        const int bx = t & 7;
        gemm_tile(fa.X, fa.WT + (size_t)3 * NWEL,
                  fa.out, nullptr, 1.0f, 0, bx, by, smem, tid);
    }
}

// ---------------------------------------------------------------------------
// Launch
// ---------------------------------------------------------------------------
extern "C" void kernel_launch(void* const* d_in, const int* in_sizes, int n_in,
                              void* d_out, int out_size)
{
    FusedArgs fa;
    fa.x[0] = (const float*)d_in[0];
    fa.x[1] = (const float*)d_in[1];
    fa.x[2] = (const float*)d_in[2];
    fa.w[0] = (const float*)d_in[3];
    fa.w[1] = (const float*)d_in[4];
    fa.w[2] = (const float*)d_in[5];
    fa.w[3] = (const float*)d_in[6];
    fa.out = (float*)d_out;

    cudaGetSymbolAddress((void**)&fa.X,  g_X);
    cudaGetSymbolAddress((void**)&fa.WT, g_WT);
    cudaGetSymbolAddress((void**)&fa.Qh, g_Qh);
    cudaGetSymbolAddress((void**)&fa.Kh, g_Kh);
    cudaGetSymbolAddress((void**)&fa.Vh, g_Vh);

    cudaFuncSetAttribute(fused_kernel,
                         cudaFuncAttributeMaxDynamicSharedMemorySize, SMEM_MAX);

    fused_kernel<<<NCTA, 256, SMEM_MAX>>>(fa);
}